// round 2
// baseline (speedup 1.0000x reference)
#include <cuda_runtime.h>

typedef unsigned long long ull;

#define Bb   2
#define Nn   512
#define Hh   1024
#define HDd  512
#define Mm   (Bb * Nn)       // 1024 rows of flattened emb
#define NOUT (3 * HDd)       // 1536 fused GEMM output columns

// Scratch (static device globals — no allocation in kernel_launch)
__device__ float g_p[Mm * HDd];      // relu(emb@W_s1 + b_s1) * w_s2   [m][d]
__device__ float g_a2T[HDd * Mm];    // (emb@W1_start + b_e1)^T        [d][m]
__device__ float g_cT[HDd * Mm];     // (emb@W1_end)^T                 [d][m]

#define FMA2(acc, a, b) asm("fma.rn.f32x2 %0, %1, %2, %0;" : "+l"(acc) : "l"(a), "l"(b))
#define UNPK(lo, hi, v) asm("mov.b64 {%0, %1}, %2;" : "=f"(lo), "=f"(hi) : "l"(v))

// ---------------------------------------------------------------------------
// Fused GEMM: C[1024,1536] = emb[1024,1024] @ [W_s1 | W_e1[:H] | W_e1[H:]]
// BM=32, BN=64, BK=16, 256 threads, micro-tile 2x4 via packed f32x2.
// Epilogues differ per 512-column block (blk uniform per CTA):
//   blk0: g_p   = relu(x + b_s1)*w_s2        (row-major)
//   blk1: g_a2T = (x + b_e1)^T               (transposed for end kernel)
//   blk2: g_cT  = x^T
// ---------------------------------------------------------------------------
__global__ __launch_bounds__(256) void gemm_kernel(
    const float* __restrict__ emb,  const float* __restrict__ W_s1,
    const float* __restrict__ b_s1, const float* __restrict__ w_s2,
    const float* __restrict__ W_e1, const float* __restrict__ b_e1)
{
    __shared__ __align__(16) float2 As[16][32];  // [k][m], value duplicated in pair
    __shared__ __align__(16) float  Bs[16][64];  // [k][n]

    const int m0    = blockIdx.y * 32;
    const int n0    = blockIdx.x * 64;
    const int blk   = n0 >> 9;          // 0,1,2
    const int bcol0 = n0 & 511;
    const float* Bsrc = (blk == 0) ? W_s1 : (W_e1 + (blk == 2 ? Hh * HDd : 0));

    const int t  = threadIdx.x;
    const int tx = t & 15;              // 4 output cols at tx*4 (2 pairs)
    const int ty = t >> 4;              // 2 output rows at ty*2

    const int ar = t >> 2, aq = t & 3;    // A loader (t < 128)
    const int bkr = t >> 4, bnq = t & 15; // B loader (all threads)

    ull acc00 = 0, acc01 = 0, acc10 = 0, acc11 = 0;

    for (int kt = 0; kt < Hh; kt += 16) {
        if (t < 128) {
            float4 v = *(const float4*)(emb + (size_t)(m0 + ar) * Hh + kt + aq * 4);
            As[aq * 4 + 0][ar] = make_float2(v.x, v.x);
            As[aq * 4 + 1][ar] = make_float2(v.y, v.y);
            As[aq * 4 + 2][ar] = make_float2(v.z, v.z);
            As[aq * 4 + 3][ar] = make_float2(v.w, v.w);
        }
        {
            float4 v = *(const float4*)(Bsrc + (size_t)(kt + bkr) * HDd + bcol0 + bnq * 4);
            *(float4*)&Bs[bkr][bnq * 4] = v;
        }
        __syncthreads();
#pragma unroll
        for (int kk = 0; kk < 16; kk++) {
            ull a0 = ((const ull*)As[kk])[ty * 2 + 0];
            ull a1 = ((const ull*)As[kk])[ty * 2 + 1];
            ulonglong2 bb = *(const ulonglong2*)&Bs[kk][tx * 4];
            FMA2(acc00, a0, bb.x); FMA2(acc01, a0, bb.y);
            FMA2(acc10, a1, bb.x); FMA2(acc11, a1, bb.y);
        }
        __syncthreads();
    }

    float c00, c01, c02, c03, c10, c11, c12, c13;
    UNPK(c00, c01, acc00); UNPK(c02, c03, acc01);
    UNPK(c10, c11, acc10); UNPK(c12, c13, acc11);

    const int d0  = bcol0 + tx * 4;     // column within the 512-wide block
    const int m_0 = m0 + ty * 2;

    if (blk == 0) {
        const float4 bs = *(const float4*)(b_s1 + d0);
        const float4 ws = *(const float4*)(w_s2 + d0);
        float4 o0, o1;
        o0.x = fmaxf(c00 + bs.x, 0.f) * ws.x;
        o0.y = fmaxf(c01 + bs.y, 0.f) * ws.y;
        o0.z = fmaxf(c02 + bs.z, 0.f) * ws.z;
        o0.w = fmaxf(c03 + bs.w, 0.f) * ws.w;
        o1.x = fmaxf(c10 + bs.x, 0.f) * ws.x;
        o1.y = fmaxf(c11 + bs.y, 0.f) * ws.y;
        o1.z = fmaxf(c12 + bs.z, 0.f) * ws.z;
        o1.w = fmaxf(c13 + bs.w, 0.f) * ws.w;
        *(float4*)(g_p + (size_t)m_0 * HDd + d0)       = o0;
        *(float4*)(g_p + (size_t)(m_0 + 1) * HDd + d0) = o1;
    } else if (blk == 1) {
        const float4 be = *(const float4*)(b_e1 + d0);
        *(float2*)(g_a2T + (size_t)(d0 + 0) * Mm + m_0) = make_float2(c00 + be.x, c10 + be.x);
        *(float2*)(g_a2T + (size_t)(d0 + 1) * Mm + m_0) = make_float2(c01 + be.y, c11 + be.y);
        *(float2*)(g_a2T + (size_t)(d0 + 2) * Mm + m_0) = make_float2(c02 + be.z, c12 + be.z);
        *(float2*)(g_a2T + (size_t)(d0 + 3) * Mm + m_0) = make_float2(c03 + be.w, c13 + be.w);
    } else {
        *(float2*)(g_cT + (size_t)(d0 + 0) * Mm + m_0) = make_float2(c00, c10);
        *(float2*)(g_cT + (size_t)(d0 + 1) * Mm + m_0) = make_float2(c01, c11);
        *(float2*)(g_cT + (size_t)(d0 + 2) * Mm + m_0) = make_float2(c02, c12);
        *(float2*)(g_cT + (size_t)(d0 + 3) * Mm + m_0) = make_float2(c03, c13);
    }
}

// ---------------------------------------------------------------------------
// start_logits[m] = sum_d g_p[m][d] + b_s2   (one warp per row)
// ---------------------------------------------------------------------------
__global__ __launch_bounds__(256) void start_kernel(
    const float* __restrict__ b_s2, float* __restrict__ out)
{
    const int warp = (blockIdx.x * 256 + threadIdx.x) >> 5;  // 0..1023
    const int lane = threadIdx.x & 31;
    const float* row = g_p + (size_t)warp * HDd;

    float s = 0.f;
#pragma unroll
    for (int k = 0; k < 4; k++) {
        float4 v = *(const float4*)(row + (lane + 32 * k) * 4);
        s += v.x + v.y + v.z + v.w;
    }
#pragma unroll
    for (int off = 16; off; off >>= 1) s += __shfl_down_sync(0xffffffffu, s, off);
    if (lane == 0) out[warp] = s + b_s2[0];
}

// ---------------------------------------------------------------------------
// end_logits[b,i,j] = sum_d relu(a2[b,i,d] + c[b,j,d]) * w_e2[d] + b_e2
// Tile 32x32 (i x j) per CTA, d chunked by 64 through smem. 128 threads,
// micro-tile 2i x 4j. a2T / cT are pre-transposed so loads are coalesced and
// smem reads conflict-free (a: 8B broadcast pairs, c: contiguous 16B/thread).
// ---------------------------------------------------------------------------
__global__ __launch_bounds__(128) void end_kernel(
    const float* __restrict__ w_e2, const float* __restrict__ b_e2,
    float* __restrict__ out_end)
{
    __shared__ __align__(16) float Asm[64][32];  // [d][i]
    __shared__ __align__(16) float Csm[64][32];  // [d][j]
    __shared__ float Wsm[HDd];

    const int t  = threadIdx.x;
    const int bz = blockIdx.z;
    const int i0 = blockIdx.y * 32;
    const int j0 = blockIdx.x * 32;
    const int mi = bz * Nn + i0;   // column base in a2T
    const int mj = bz * Nn + j0;   // column base in cT

    for (int d = t; d < HDd; d += 128) Wsm[d] = w_e2[d];

    const int tx = t & 7;          // j micro: tx*4 .. +3
    const int ty = t >> 3;         // i micro: ty*2 .. +1
    const int ldr = t >> 3;        // loader d-row base (0..15)
    const int ldq = t & 7;         // loader float4 index (0..7 over 32 cols)

    float a00 = 0.f, a01 = 0.f, a02 = 0.f, a03 = 0.f;
    float a10 = 0.f, a11 = 0.f, a12 = 0.f, a13 = 0.f;

    for (int dc0 = 0; dc0 < HDd; dc0 += 64) {
        __syncthreads();
#pragma unroll
        for (int rep = 0; rep < 4; rep++) {
            int drow = rep * 16 + ldr;
            float4 va = *(const float4*)(g_a2T + (size_t)(dc0 + drow) * Mm + mi + ldq * 4);
            float4 vc = *(const float4*)(g_cT  + (size_t)(dc0 + drow) * Mm + mj + ldq * 4);
            *(float4*)&Asm[drow][ldq * 4] = va;
            *(float4*)&Csm[drow][ldq * 4] = vc;
        }
        __syncthreads();
#pragma unroll 8
        for (int dc = 0; dc < 64; dc++) {
            float w   = Wsm[dc0 + dc];
            float2 av = *(const float2*)&Asm[dc][ty * 2];
            float4 cv = *(const float4*)&Csm[dc][tx * 4];
            a00 = fmaf(fmaxf(av.x + cv.x, 0.f), w, a00);
            a01 = fmaf(fmaxf(av.x + cv.y, 0.f), w, a01);
            a02 = fmaf(fmaxf(av.x + cv.z, 0.f), w, a02);
            a03 = fmaf(fmaxf(av.x + cv.w, 0.f), w, a03);
            a10 = fmaf(fmaxf(av.y + cv.x, 0.f), w, a10);
            a11 = fmaf(fmaxf(av.y + cv.y, 0.f), w, a11);
            a12 = fmaf(fmaxf(av.y + cv.z, 0.f), w, a12);
            a13 = fmaf(fmaxf(av.y + cv.w, 0.f), w, a13);
        }
    }

    const float be = b_e2[0];
    float4 o0 = make_float4(a00 + be, a01 + be, a02 + be, a03 + be);
    float4 o1 = make_float4(a10 + be, a11 + be, a12 + be, a13 + be);
    size_t base = (size_t)bz * Nn * Nn + (size_t)(i0 + ty * 2) * Nn + j0 + tx * 4;
    *(float4*)(out_end + base)      = o0;
    *(float4*)(out_end + base + Nn) = o1;
}

// ---------------------------------------------------------------------------
extern "C" void kernel_launch(void* const* d_in, const int* in_sizes, int n_in,
                              void* d_out, int out_size)
{
    (void)in_sizes; (void)n_in; (void)out_size;
    const float* emb  = (const float*)d_in[0];
    const float* W_s1 = (const float*)d_in[1];
    const float* b_s1 = (const float*)d_in[2];
    const float* w_s2 = (const float*)d_in[3];
    const float* b_s2 = (const float*)d_in[4];
    const float* W_e1 = (const float*)d_in[5];
    const float* b_e1 = (const float*)d_in[6];
    const float* w_e2 = (const float*)d_in[7];
    const float* b_e2 = (const float*)d_in[8];
    float* out = (float*)d_out;

    dim3 gg(NOUT / 64, Mm / 32);          // 24 x 32 = 768 CTAs
    gemm_kernel<<<gg, 256>>>(emb, W_s1, b_s1, w_s2, W_e1, b_e1);

    start_kernel<<<Mm / 8, 256>>>(b_s2, out);

    dim3 ge(Nn / 32, Nn / 32, Bb);        // 16 x 16 x 2 = 512 CTAs
    end_kernel<<<ge, 128>>>(w_e2, b_e2, out + Mm);
}

// round 4
// speedup vs baseline: 3.4431x; 3.4431x over previous
#include <cuda_runtime.h>
#include <cuda_fp16.h>
#include <cstdint>

typedef unsigned long long ull;

#define Bb   2
#define Nn   512
#define Hh   1024
#define HDd  512
#define Mm   1024          // B*N rows
#define NTOT 1536          // fused GEMM output columns

// GEMM tiling
#define BM 128
#define BN 128
#define BK 64
#define KT (Hh / BK)             // 16 k-tiles
#define STG 32768                // A(16KB)+B(16KB) per stage
#define EP_PITCH 130             // epilogue smem pitch (floats)
#define SMEM_DYN (BM * EP_PITCH * 4)   // 66560 >= 2*STG

// -------- scratch --------
__device__ __half g_Ah[Mm * Hh];            // emb in fp16
__device__ __half g_Bh[NTOT * Hh];          // weights transposed [n][k], fp16
__device__ float  g_a2T[HDd * Mm];          // (emb@W1_start + b_e1)^T  [d][m]
__device__ float  g_cT[HDd * Mm];           // (emb@W1_end)^T           [d][m]

// -------- PTX helpers --------
__device__ __forceinline__ uint32_t smem_u32(const void* p) {
    uint32_t a;
    asm("{ .reg .u64 t; cvta.to.shared.u64 t, %1; cvt.u32.u64 %0, t; }" : "=r"(a) : "l"(p));
    return a;
}
#define CP16(dst, src) \
    asm volatile("cp.async.cg.shared.global [%0], [%1], 16;" :: "r"(dst), "l"(src) : "memory")
#define CP_COMMIT() asm volatile("cp.async.commit_group;" ::: "memory")

#define LDSM4(r0, r1, r2, r3, a) \
    asm volatile("ldmatrix.sync.aligned.m8n8.x4.shared.b16 {%0,%1,%2,%3}, [%4];" \
        : "=r"(r0), "=r"(r1), "=r"(r2), "=r"(r3) : "r"(a))

#define MMA16816(d, a0, a1, a2, a3, b0, b1) \
    asm volatile("mma.sync.aligned.m16n8k16.row.col.f32.f16.f16.f32 " \
        "{%0,%1,%2,%3}, {%4,%5,%6,%7}, {%8,%9}, {%0,%1,%2,%3};" \
        : "+f"((d)[0]), "+f"((d)[1]), "+f"((d)[2]), "+f"((d)[3]) \
        : "r"(a0), "r"(a1), "r"(a2), "r"(a3), "r"(b0), "r"(b1))

// -------- prepass: emb -> fp16 --------
__global__ __launch_bounds__(256) void esplit_kernel(const float* __restrict__ emb) {
    int i = blockIdx.x * 256 + threadIdx.x;        // float4 index, 262144 total
    float4 v = ((const float4*)emb)[i];
    __half2* A = (__half2*)g_Ah;
    A[2 * i]     = __floats2half2_rn(v.x, v.y);
    A[2 * i + 1] = __floats2half2_rn(v.z, v.w);
}

// -------- prepass: transpose weights -> g_Bh[n][k] fp16 --------
__global__ __launch_bounds__(256) void wsplit_kernel(const float* __restrict__ W_s1,
                                                     const float* __restrict__ W_e1) {
    __shared__ float sm[32][33];
    const int n0 = blockIdx.x * 32, k0 = blockIdx.y * 32;
    const int t = threadIdx.x, c = t & 31, r = t >> 5;
#pragma unroll
    for (int p = 0; p < 4; p++) {
        int k = k0 + r + 8 * p, n = n0 + c;
        float v;
        if (n < 512)       v = W_s1[(size_t)k * 512 + n];
        else if (n < 1024) v = W_e1[(size_t)k * 512 + (n - 512)];
        else               v = W_e1[(size_t)(1024 + k) * 512 + (n - 1024)];
        sm[r + 8 * p][c] = v;   // sm[k_local][n_local]
    }
    __syncthreads();
#pragma unroll
    for (int p = 0; p < 4; p++) {
        int ln = r + 8 * p, lk = c;
        g_Bh[(size_t)(n0 + ln) * Hh + k0 + lk] = __float2half_rn(sm[lk][ln]);
    }
}

__global__ void init_out_kernel(const float* __restrict__ b_s2, float* __restrict__ out) {
    int i = blockIdx.x * 256 + threadIdx.x;
    if (i < Mm) out[i] = b_s2[0];
}

// -------- HMMA GEMM: C[1024,1536] = emb_fp16 @ [W_s1|W_e1a|W_e1b]_fp16 --------
__device__ __forceinline__ void load_stage(uint32_t abase, const __half* __restrict__ A,
                                           const __half* __restrict__ B, int kt, int tid) {
    const uint32_t bbase = abase + 16384;
#pragma unroll
    for (int i = 0; i < 4; i++) {
        int c = tid + i * 256;             // 1024 16B chunks for A
        int row = c >> 3, kc = c & 7;
        uint32_t dst = abase + (uint32_t)(row * 128) + (uint32_t)((kc ^ (row & 7)) << 4);
        CP16(dst, A + (size_t)row * Hh + kt * BK + kc * 8);
    }
#pragma unroll
    for (int i = 0; i < 4; i++) {
        int c = tid + i * 256;
        int row = c >> 3, kc = c & 7;
        uint32_t dst = bbase + (uint32_t)(row * 128) + (uint32_t)((kc ^ (row & 7)) << 4);
        CP16(dst, B + (size_t)row * Hh + kt * BK + kc * 8);
    }
}

__global__ __launch_bounds__(256, 1) void gemm_kernel(
    const float* __restrict__ b_s1, const float* __restrict__ w_s2,
    const float* __restrict__ b_e1, float* __restrict__ out)
{
    extern __shared__ char smem[];
    const uint32_t sb = smem_u32(smem);

    const int tid = threadIdx.x, lane = tid & 31, wid = tid >> 5;
    const int wm = wid & 3;                 // warp row group (32 rows)
    const int wn = wid >> 2;                // warp col group (64 cols)
    const int m0 = blockIdx.y * BM;
    const int n0 = blockIdx.x * BN;
    const __half* Ap = g_Ah + (size_t)m0 * Hh;
    const __half* Bp = g_Bh + (size_t)n0 * Hh;

    float acc[2][8][4];
#pragma unroll
    for (int i = 0; i < 2; i++)
#pragma unroll
        for (int j = 0; j < 8; j++)
#pragma unroll
            for (int r = 0; r < 4; r++) acc[i][j][r] = 0.f;

    // ldmatrix lane addressing (within a stage base)
    const int a_row = wm * 32 + (lane & 15);          // +16 for second m-tile
    const int b_row = wn * 64 + (lane & 15);          // +16j for n-groups
    const int l_kc  = lane >> 4;                      // 0/1 k-chunk half

    load_stage(sb, Ap, Bp, 0, tid);
    CP_COMMIT();

    for (int t = 0; t < KT; t++) {
        if (t + 1 < KT) {
            load_stage(sb + (uint32_t)(((t + 1) & 1) * STG), Ap, Bp, t + 1, tid);
            CP_COMMIT();
            asm volatile("cp.async.wait_group 1;" ::: "memory");
        } else {
            asm volatile("cp.async.wait_group 0;" ::: "memory");
        }
        __syncthreads();

        const uint32_t Ab = sb + (uint32_t)((t & 1) * STG);
        const uint32_t Bbs = Ab + 16384;
#pragma unroll
        for (int ks = 0; ks < 4; ks++) {              // 4 k16-steps in BK=64
            const int kc = 2 * ks + l_kc;
            uint32_t a0r[4], a1r[4];
            {
                int r = a_row;
                LDSM4(a0r[0], a0r[1], a0r[2], a0r[3],
                      Ab + (uint32_t)(r * 128) + (uint32_t)((kc ^ (r & 7)) << 4));
                r = a_row + 16;
                LDSM4(a1r[0], a1r[1], a1r[2], a1r[3],
                      Ab + (uint32_t)(r * 128) + (uint32_t)((kc ^ (r & 7)) << 4));
            }
#pragma unroll
            for (int j = 0; j < 4; j++) {             // 4 n16-groups = 8 n8-tiles
                int r = b_row + 16 * j;
                uint32_t b0, b1, b2, b3;
                LDSM4(b0, b1, b2, b3,
                      Bbs + (uint32_t)(r * 128) + (uint32_t)((kc ^ (r & 7)) << 4));
                MMA16816(acc[0][2 * j],     a0r[0], a0r[1], a0r[2], a0r[3], b0, b2);
                MMA16816(acc[0][2 * j + 1], a0r[0], a0r[1], a0r[2], a0r[3], b1, b3);
                MMA16816(acc[1][2 * j],     a1r[0], a1r[1], a1r[2], a1r[3], b0, b2);
                MMA16816(acc[1][2 * j + 1], a1r[0], a1r[1], a1r[2], a1r[3], b1, b3);
            }
        }
        __syncthreads();
    }

    // ---- dump accumulators to smem [BM][EP_PITCH] ----
    float* eps = (float*)smem;
    const int rbase = wm * 32 + (lane >> 2);
    const int cbase = wn * 64 + (lane & 3) * 2;
#pragma unroll
    for (int i = 0; i < 2; i++)
#pragma unroll
        for (int j = 0; j < 8; j++) {
            int rr = rbase + i * 16;
            int cc = cbase + j * 8;
            *(float2*)&eps[rr * EP_PITCH + cc]       = make_float2(acc[i][j][0], acc[i][j][1]);
            *(float2*)&eps[(rr + 8) * EP_PITCH + cc] = make_float2(acc[i][j][2], acc[i][j][3]);
        }
    __syncthreads();

    // ---- epilogue ----
    const int blk = n0 >> 9;                 // 0 / 1 / 2
    const int cb  = n0 & 511;
    if (blk == 0) {
        // start logits partial: relu(x + b_s1)*w_s2 summed over this CTA's 128 cols
        const int r = tid >> 1, h = tid & 1;
        float s = 0.f;
#pragma unroll 16
        for (int c = 0; c < 64; c++) {
            int d = cb + h * 64 + c;
            s += fmaxf(eps[r * EP_PITCH + h * 64 + c] + __ldg(b_s1 + d), 0.f) * __ldg(w_s2 + d);
        }
        s += __shfl_xor_sync(0xffffffffu, s, 1);
        if (h == 0) atomicAdd(out + m0 + r, s);
    } else {
        float* dst = (blk == 1) ? g_a2T : g_cT;
#pragma unroll 8
        for (int it = 0; it < 64; it++) {
            int idx = it * 256 + tid;
            int m = idx & 127, dl = idx >> 7;
            int d = cb + dl;
            float v = eps[m * EP_PITCH + dl] + ((blk == 1) ? __ldg(b_e1 + d) : 0.f);
            dst[(size_t)d * Mm + m0 + m] = v;
        }
    }
}

// -------- end logits: packed f32x2 relu-reduction --------
#define RELUFMA(acc, a2, c2, w2) \
    asm("{\n\t.reg .f32 lo, hi; .reg .b64 s, m;\n\t" \
        "add.rn.f32x2 s, %1, %2;\n\t" \
        "mov.b64 {lo, hi}, s;\n\t" \
        "max.f32 lo, lo, 0f00000000;\n\t" \
        "max.f32 hi, hi, 0f00000000;\n\t" \
        "mov.b64 m, {lo, hi};\n\t" \
        "fma.rn.f32x2 %0, m, %3, %0;\n\t}" \
        : "+l"(acc) : "l"(a2), "l"(c2), "l"(w2))

__global__ __launch_bounds__(256) void end_kernel(
    const float* __restrict__ w_e2, const float* __restrict__ b_e2,
    float* __restrict__ out_end)
{
    __shared__ __align__(16) float Asm[32][64];     // [d][i]
    __shared__ __align__(16) float Csm[32][128];    // [d][dup pairs, split halves]
    __shared__ __align__(8)  float2 Wsm[HDd];       // (w,w)

    const int t = threadIdx.x;
    const int bz = blockIdx.z;
    const int i0 = blockIdx.y * 64, j0 = blockIdx.x * 64;
    const int mi = bz * Nn + i0, mj = bz * Nn + j0;

    for (int d = t; d < HDd; d += 256) { float w = w_e2[d]; Wsm[d] = make_float2(w, w); }

    const int tx = t & 15;          // j-group (4 j)
    const int ty = t >> 4;          // i-group (4 i)

    ull acc[2][4];
#pragma unroll
    for (int a = 0; a < 2; a++)
#pragma unroll
        for (int b = 0; b < 4; b++) acc[a][b] = 0;

    for (int dc0 = 0; dc0 < HDd; dc0 += 32) {
        __syncthreads();
#pragma unroll
        for (int rep = 0; rep < 2; rep++) {
            int i = rep * 256 + t;
            int dk = i >> 4, q = i & 15;
            float4 va = *(const float4*)(g_a2T + (size_t)(dc0 + dk) * Mm + mi + q * 4);
            float4 vc = *(const float4*)(g_cT  + (size_t)(dc0 + dk) * Mm + mj + q * 4);
            *(float4*)&Asm[dk][q * 4] = va;
            *(float4*)&Csm[dk][q * 4]      = make_float4(vc.x, vc.x, vc.y, vc.y);
            *(float4*)&Csm[dk][64 + q * 4] = make_float4(vc.z, vc.z, vc.w, vc.w);
        }
        __syncthreads();
#pragma unroll 4
        for (int dc = 0; dc < 32; dc++) {
            ull w2 = *(const ull*)&Wsm[dc0 + dc];
            ulonglong2 ap  = *(const ulonglong2*)&Asm[dc][ty * 4];
            ulonglong2 c01 = *(const ulonglong2*)&Csm[dc][tx * 4];
            ulonglong2 c23 = *(const ulonglong2*)&Csm[dc][64 + tx * 4];
            RELUFMA(acc[0][0], ap.x, c01.x, w2);
            RELUFMA(acc[0][1], ap.x, c01.y, w2);
            RELUFMA(acc[0][2], ap.x, c23.x, w2);
            RELUFMA(acc[0][3], ap.x, c23.y, w2);
            RELUFMA(acc[1][0], ap.y, c01.x, w2);
            RELUFMA(acc[1][1], ap.y, c01.y, w2);
            RELUFMA(acc[1][2], ap.y, c23.x, w2);
            RELUFMA(acc[1][3], ap.y, c23.y, w2);
        }
    }

    const float be = b_e2[0];
#pragma unroll
    for (int pi = 0; pi < 2; pi++) {
        float lo[4], hi[4];
#pragma unroll
        for (int j = 0; j < 4; j++)
            asm("mov.b64 {%0, %1}, %2;" : "=f"(lo[j]), "=f"(hi[j]) : "l"(acc[pi][j]));
        size_t r0 = (size_t)bz * Nn * Nn + (size_t)(i0 + ty * 4 + 2 * pi) * Nn + j0 + tx * 4;
        *(float4*)(out_end + r0)      = make_float4(lo[0] + be, lo[1] + be, lo[2] + be, lo[3] + be);
        *(float4*)(out_end + r0 + Nn) = make_float4(hi[0] + be, hi[1] + be, hi[2] + be, hi[3] + be);
    }
}

// -------- host --------
extern "C" void kernel_launch(void* const* d_in, const int* in_sizes, int n_in,
                              void* d_out, int out_size)
{
    (void)in_sizes; (void)n_in; (void)out_size;
    const float* emb  = (const float*)d_in[0];
    const float* W_s1 = (const float*)d_in[1];
    const float* b_s1 = (const float*)d_in[2];
    const float* w_s2 = (const float*)d_in[3];
    const float* b_s2 = (const float*)d_in[4];
    const float* W_e1 = (const float*)d_in[5];
    const float* b_e1 = (const float*)d_in[6];
    const float* w_e2 = (const float*)d_in[7];
    const float* b_e2 = (const float*)d_in[8];
    float* out = (float*)d_out;

    static bool attr_done = false;
    if (!attr_done) {
        cudaFuncSetAttribute(gemm_kernel, cudaFuncAttributeMaxDynamicSharedMemorySize, SMEM_DYN);
        attr_done = true;
    }

    esplit_kernel<<<(Mm * Hh / 4) / 256, 256>>>(emb);
    wsplit_kernel<<<dim3(NTOT / 32, Hh / 32), 256>>>(W_s1, W_e1);
    init_out_kernel<<<(Mm + 255) / 256, 256>>>(b_s2, out);

    dim3 gg(NTOT / BN, Mm / BM);                  // 12 x 8 = 96 CTAs
    gemm_kernel<<<gg, 256, SMEM_DYN>>>(b_s1, w_s2, b_e1, out);

    dim3 ge(Nn / 64, Nn / 64, Bb);                // 8 x 8 x 2 = 128 CTAs
    end_kernel<<<ge, 256>>>(w_e2, b_e2, out + Mm);
}

// round 5
// speedup vs baseline: 3.8735x; 1.1250x over previous
#include <cuda_runtime.h>
#include <cuda_fp16.h>
#include <cstdint>

typedef unsigned long long ull;

#define Bb   2
#define Nn   512
#define Hh   1024
#define HDd  512
#define Mm   1024          // B*N rows
#define NTOT 1536          // fused GEMM output columns

// GEMM tiling
#define BM 128
#define BN 64
#define BK 64
#define KT (Hh / BK)             // 16 k-tiles
#define STG 24576                // A(16KB)+B(8KB) per stage
#define EP_PITCH 66              // epilogue smem pitch (floats)
#define GEMM_SMEM (2 * STG)      // 49152 >= 128*66*4 = 33792

// end kernel smem: W(4KB) + A 2x16KB + C 2x8KB = 53248
#define END_SMEM ((1024 + 2 * 4096 + 2 * 2048) * 4)

// -------- scratch --------
__device__ __half g_Ah[Mm * Hh];            // emb in fp16
__device__ __half g_Bh[NTOT * Hh];          // weights transposed [n][k], fp16
__device__ float  g_aD[HDd * 2 * Mm];       // (emb@W1_start + b_e1)^T duplicated: [d][2m]=(v,v)
__device__ float  g_cT[HDd * Mm];           // (emb@W1_end)^T  [d][m]

// -------- PTX helpers --------
__device__ __forceinline__ uint32_t smem_u32(const void* p) {
    uint32_t a;
    asm("{ .reg .u64 t; cvta.to.shared.u64 t, %1; cvt.u32.u64 %0, t; }" : "=r"(a) : "l"(p));
    return a;
}
#define CP16(dst, src) \
    asm volatile("cp.async.cg.shared.global [%0], [%1], 16;" :: "r"(dst), "l"(src) : "memory")
#define CP_COMMIT() asm volatile("cp.async.commit_group;" ::: "memory")

#define LDSM4(r0, r1, r2, r3, a) \
    asm volatile("ldmatrix.sync.aligned.m8n8.x4.shared.b16 {%0,%1,%2,%3}, [%4];" \
        : "=r"(r0), "=r"(r1), "=r"(r2), "=r"(r3) : "r"(a))

#define MMA16816(d, a0, a1, a2, a3, b0, b1) \
    asm volatile("mma.sync.aligned.m16n8k16.row.col.f32.f16.f16.f32 " \
        "{%0,%1,%2,%3}, {%4,%5,%6,%7}, {%8,%9}, {%0,%1,%2,%3};" \
        : "+f"((d)[0]), "+f"((d)[1]), "+f"((d)[2]), "+f"((d)[3]) \
        : "r"(a0), "r"(a1), "r"(a2), "r"(a3), "r"(b0), "r"(b1))

// -------- prepass: emb -> fp16, plus start-logit output init --------
__global__ __launch_bounds__(256) void esplit_kernel(const float* __restrict__ emb,
                                                     const float* __restrict__ b_s2,
                                                     float* __restrict__ out) {
    int i = blockIdx.x * 256 + threadIdx.x;        // float4 index, 262144 total
    float4 v = ((const float4*)emb)[i];
    __half2* A = (__half2*)g_Ah;
    A[2 * i]     = __floats2half2_rn(v.x, v.y);
    A[2 * i + 1] = __floats2half2_rn(v.z, v.w);
    if (i < Mm) out[i] = b_s2[0];
}

// -------- prepass: transpose weights -> g_Bh[n][k] fp16 --------
__global__ __launch_bounds__(256) void wsplit_kernel(const float* __restrict__ W_s1,
                                                     const float* __restrict__ W_e1) {
    __shared__ float sm[32][33];
    const int n0 = blockIdx.x * 32, k0 = blockIdx.y * 32;
    const int t = threadIdx.x, c = t & 31, r = t >> 5;
#pragma unroll
    for (int p = 0; p < 4; p++) {
        int k = k0 + r + 8 * p, n = n0 + c;
        float v;
        if (n < 512)       v = W_s1[(size_t)k * 512 + n];
        else if (n < 1024) v = W_e1[(size_t)k * 512 + (n - 512)];
        else               v = W_e1[(size_t)(1024 + k) * 512 + (n - 1024)];
        sm[r + 8 * p][c] = v;   // sm[k_local][n_local]
    }
    __syncthreads();
#pragma unroll
    for (int p = 0; p < 4; p++) {
        int ln = r + 8 * p, lk = c;
        g_Bh[(size_t)(n0 + ln) * Hh + k0 + lk] = __float2half_rn(sm[lk][ln]);
    }
}

// -------- HMMA GEMM: C[1024,1536] = emb_fp16 @ [W_s1|W_e1a|W_e1b]_fp16 --------
__device__ __forceinline__ void load_stage(uint32_t abase, const __half* __restrict__ A,
                                           const __half* __restrict__ B, int kt, int tid) {
    const uint32_t bbase = abase + 16384;
#pragma unroll
    for (int i = 0; i < 4; i++) {
        int c = tid + i * 256;             // 1024 16B chunks for A (128 rows x 8)
        int row = c >> 3, kc = c & 7;
        uint32_t dst = abase + (uint32_t)(row * 128) + (uint32_t)((kc ^ (row & 7)) << 4);
        CP16(dst, A + (size_t)row * Hh + kt * BK + kc * 8);
    }
#pragma unroll
    for (int i = 0; i < 2; i++) {
        int c = tid + i * 256;             // 512 chunks for B (64 rows x 8)
        int row = c >> 3, kc = c & 7;
        uint32_t dst = bbase + (uint32_t)(row * 128) + (uint32_t)((kc ^ (row & 7)) << 4);
        CP16(dst, B + (size_t)row * Hh + kt * BK + kc * 8);
    }
}

__global__ __launch_bounds__(256, 2) void gemm_kernel(
    const float* __restrict__ b_s1, const float* __restrict__ w_s2,
    const float* __restrict__ b_e1, float* __restrict__ out)
{
    extern __shared__ char smem[];
    const uint32_t sb = smem_u32(smem);

    const int tid = threadIdx.x, lane = tid & 31, wid = tid >> 5;
    const int wm = wid & 3;                 // warp row group (32 rows)
    const int wn = wid >> 2;                // warp col group (32 cols)
    const int m0 = blockIdx.y * BM;
    const int n0 = blockIdx.x * BN;
    const __half* Ap = g_Ah + (size_t)m0 * Hh;
    const __half* Bp = g_Bh + (size_t)n0 * Hh;

    float acc[2][4][4];
#pragma unroll
    for (int i = 0; i < 2; i++)
#pragma unroll
        for (int j = 0; j < 4; j++)
#pragma unroll
            for (int r = 0; r < 4; r++) acc[i][j][r] = 0.f;

    const int a_row = wm * 32 + (lane & 15);
    const int b_rowb = wn * 32 + (lane & 15);
    const int l_kc  = lane >> 4;

    load_stage(sb, Ap, Bp, 0, tid);
    CP_COMMIT();

    for (int t = 0; t < KT; t++) {
        if (t + 1 < KT) {
            load_stage(sb + (uint32_t)(((t + 1) & 1) * STG), Ap, Bp, t + 1, tid);
            CP_COMMIT();
            asm volatile("cp.async.wait_group 1;" ::: "memory");
        } else {
            asm volatile("cp.async.wait_group 0;" ::: "memory");
        }
        __syncthreads();

        const uint32_t Ab = sb + (uint32_t)((t & 1) * STG);
        const uint32_t Bbs = Ab + 16384;
#pragma unroll
        for (int ks = 0; ks < 4; ks++) {              // 4 k16-steps in BK=64
            const int kc = 2 * ks + l_kc;
            uint32_t a0r[4], a1r[4];
            {
                int r = a_row;
                LDSM4(a0r[0], a0r[1], a0r[2], a0r[3],
                      Ab + (uint32_t)(r * 128) + (uint32_t)((kc ^ (r & 7)) << 4));
                r = a_row + 16;
                LDSM4(a1r[0], a1r[1], a1r[2], a1r[3],
                      Ab + (uint32_t)(r * 128) + (uint32_t)((kc ^ (r & 7)) << 4));
            }
#pragma unroll
            for (int jg = 0; jg < 2; jg++) {          // 2 n16-groups = 4 n8-tiles
                int r = b_rowb + 16 * jg;
                uint32_t b0, b1, b2, b3;
                LDSM4(b0, b1, b2, b3,
                      Bbs + (uint32_t)(r * 128) + (uint32_t)((kc ^ (r & 7)) << 4));
                MMA16816(acc[0][2 * jg],     a0r[0], a0r[1], a0r[2], a0r[3], b0, b2);
                MMA16816(acc[0][2 * jg + 1], a0r[0], a0r[1], a0r[2], a0r[3], b1, b3);
                MMA16816(acc[1][2 * jg],     a1r[0], a1r[1], a1r[2], a1r[3], b0, b2);
                MMA16816(acc[1][2 * jg + 1], a1r[0], a1r[1], a1r[2], a1r[3], b1, b3);
            }
        }
        __syncthreads();
    }

    // ---- dump accumulators to smem [BM][EP_PITCH] ----
    float* eps = (float*)smem;
    const int rbase = wm * 32 + (lane >> 2);
    const int cbase = wn * 32 + (lane & 3) * 2;
#pragma unroll
    for (int i = 0; i < 2; i++)
#pragma unroll
        for (int j = 0; j < 4; j++) {
            int rr = rbase + i * 16;
            int cc = cbase + j * 8;
            *(float2*)&eps[rr * EP_PITCH + cc]       = make_float2(acc[i][j][0], acc[i][j][1]);
            *(float2*)&eps[(rr + 8) * EP_PITCH + cc] = make_float2(acc[i][j][2], acc[i][j][3]);
        }
    __syncthreads();

    // ---- epilogue ----
    const int blk = n0 >> 9;                 // 0 / 1 / 2
    const int cb  = n0 & 511;
    if (blk == 0) {
        // start logits partial: relu(x + b_s1)*w_s2 summed over this CTA's 64 cols
        const int r = tid >> 1, h = tid & 1;
        float s = 0.f;
#pragma unroll 8
        for (int c = 0; c < 32; c++) {
            int d = cb + h * 32 + c;
            s += fmaxf(eps[r * EP_PITCH + h * 32 + c] + __ldg(b_s1 + d), 0.f) * __ldg(w_s2 + d);
        }
        s += __shfl_xor_sync(0xffffffffu, s, 1);
        if (h == 0) atomicAdd(out + m0 + r, s);
    } else if (blk == 1) {
        // a-part: write duplicated transposed rows for the end kernel
#pragma unroll 4
        for (int it = 0; it < 32; it++) {
            int idx = it * 256 + tid;            // 8192 = 128m x 64d
            int m = idx & 127, dl = idx >> 7;
            int d = cb + dl;
            float v = eps[m * EP_PITCH + dl] + __ldg(b_e1 + d);
            *(float2*)(g_aD + (size_t)d * (2 * Mm) + 2 * (m0 + m)) = make_float2(v, v);
        }
    } else {
#pragma unroll 4
        for (int it = 0; it < 32; it++) {
            int idx = it * 256 + tid;
            int m = idx & 127, dl = idx >> 7;
            g_cT[(size_t)(cb + dl) * Mm + m0 + m] = eps[m * EP_PITCH + dl];
        }
    }
}

// -------- end logits: packed f32x2 relu-reduction, cp.async pipelined --------
#define RELUFMA(acc, a2, c2, w2) \
    asm("{\n\t.reg .f32 lo, hi; .reg .b64 s, m;\n\t" \
        "add.rn.f32x2 s, %1, %2;\n\t" \
        "mov.b64 {lo, hi}, s;\n\t" \
        "max.f32 lo, lo, 0f00000000;\n\t" \
        "max.f32 hi, hi, 0f00000000;\n\t" \
        "mov.b64 m, {lo, hi};\n\t" \
        "fma.rn.f32x2 %0, m, %3, %0;\n\t}" \
        : "+l"(acc) : "l"(a2), "l"(c2), "l"(w2))

__global__ __launch_bounds__(256) void end_kernel(
    const float* __restrict__ w_e2, const float* __restrict__ b_e2,
    float* __restrict__ out_end)
{
    extern __shared__ float sf[];
    // layout (floats): W dup [1024] | A stages [2][4096] | C stages [2][2048]
    float2* Wsm = (float2*)sf;
    const uint32_t sb = smem_u32(sf);
    const uint32_t AOFF = 1024 * 4;
    const uint32_t COFF = AOFF + 2 * 4096 * 4;

    const int t = threadIdx.x;
    const int bz = blockIdx.z;
    const int i0 = blockIdx.y * 64, j0 = blockIdx.x * 64;
    const int mi = bz * Nn + i0, mj = bz * Nn + j0;

    for (int d = t; d < 512; d += 256) { float w = w_e2[d]; Wsm[d] = make_float2(w, w); }

    const int tx = t & 15;          // j-group: 4 j at tx*4
    const int ty = t >> 4;          // i-group: 4 i at ty*4

    const float* Asrc0 = g_aD + 2 * mi;
    const float* Csrc0 = g_cT + mj;

    ull acc[4][2];
#pragma unroll
    for (int a = 0; a < 4; a++) { acc[a][0] = 0; acc[a][1] = 0; }

#define LOAD_CHUNK(ch) do { \
    const int _st = (ch) & 1; \
    const uint32_t _Ab = sb + AOFF + (uint32_t)(_st * 4096 * 4); \
    const uint32_t _Cb = sb + COFF + (uint32_t)(_st * 2048 * 4); \
    const float* _As = Asrc0 + (size_t)((ch) * 32) * 2048; \
    const float* _Cs = Csrc0 + (size_t)((ch) * 32) * 1024; \
    _Pragma("unroll") \
    for (int _i = 0; _i < 4; _i++) { \
        int _c = t + _i * 256; \
        int _r = _c >> 5, _q = _c & 31; \
        CP16(_Ab + (uint32_t)(_r * 512 + _q * 16), _As + (size_t)_r * 2048 + _q * 4); \
    } \
    _Pragma("unroll") \
    for (int _i = 0; _i < 2; _i++) { \
        int _c = t + _i * 256; \
        int _r = _c >> 4, _q = _c & 15; \
        CP16(_Cb + (uint32_t)(_r * 256 + _q * 16), _Cs + (size_t)_r * 1024 + _q * 4); \
    } \
} while (0)

    LOAD_CHUNK(0);
    CP_COMMIT();

    for (int ch = 0; ch < 16; ch++) {
        if (ch + 1 < 16) {
            LOAD_CHUNK(ch + 1);
            CP_COMMIT();
            asm volatile("cp.async.wait_group 1;" ::: "memory");
        } else {
            asm volatile("cp.async.wait_group 0;" ::: "memory");
        }
        __syncthreads();

        const int st = ch & 1;
        const float* Abuf = sf + 1024 + st * 4096;
        const float* Cbuf = sf + 1024 + 2 * 4096 + st * 2048;
#pragma unroll 4
        for (int dc = 0; dc < 32; dc++) {
            ull w2 = *(const ull*)&Wsm[ch * 32 + dc];
            const float* ar = Abuf + dc * 128 + ty * 8;
            ulonglong2 aP0 = *(const ulonglong2*)ar;          // dup pairs (i0),(i1)
            ulonglong2 aP1 = *(const ulonglong2*)(ar + 4);    // dup pairs (i2),(i3)
            ulonglong2 cP  = *(const ulonglong2*)(Cbuf + dc * 64 + tx * 4);  // (c0,c1),(c2,c3)
            RELUFMA(acc[0][0], aP0.x, cP.x, w2); RELUFMA(acc[0][1], aP0.x, cP.y, w2);
            RELUFMA(acc[1][0], aP0.y, cP.x, w2); RELUFMA(acc[1][1], aP0.y, cP.y, w2);
            RELUFMA(acc[2][0], aP1.x, cP.x, w2); RELUFMA(acc[2][1], aP1.x, cP.y, w2);
            RELUFMA(acc[3][0], aP1.y, cP.x, w2); RELUFMA(acc[3][1], aP1.y, cP.y, w2);
        }
        __syncthreads();
    }

    const float be = b_e2[0];
#pragma unroll
    for (int i = 0; i < 4; i++) {
        float l0, h0, l1, h1;
        asm("mov.b64 {%0, %1}, %2;" : "=f"(l0), "=f"(h0) : "l"(acc[i][0]));
        asm("mov.b64 {%0, %1}, %2;" : "=f"(l1), "=f"(h1) : "l"(acc[i][1]));
        size_t r0 = (size_t)bz * Nn * Nn + (size_t)(i0 + ty * 4 + i) * Nn + j0 + tx * 4;
        *(float4*)(out_end + r0) = make_float4(l0 + be, h0 + be, l1 + be, h1 + be);
    }
}

// -------- host --------
extern "C" void kernel_launch(void* const* d_in, const int* in_sizes, int n_in,
                              void* d_out, int out_size)
{
    (void)in_sizes; (void)n_in; (void)out_size;
    const float* emb  = (const float*)d_in[0];
    const float* W_s1 = (const float*)d_in[1];
    const float* b_s1 = (const float*)d_in[2];
    const float* w_s2 = (const float*)d_in[3];
    const float* b_s2 = (const float*)d_in[4];
    const float* W_e1 = (const float*)d_in[5];
    const float* b_e1 = (const float*)d_in[6];
    const float* w_e2 = (const float*)d_in[7];
    const float* b_e2 = (const float*)d_in[8];
    float* out = (float*)d_out;

    static bool attr_done = false;
    if (!attr_done) {
        cudaFuncSetAttribute(gemm_kernel, cudaFuncAttributeMaxDynamicSharedMemorySize, GEMM_SMEM);
        cudaFuncSetAttribute(end_kernel, cudaFuncAttributeMaxDynamicSharedMemorySize, END_SMEM);
        attr_done = true;
    }

    esplit_kernel<<<(Mm * Hh / 4) / 256, 256>>>(emb, b_s2, out);
    wsplit_kernel<<<dim3(NTOT / 32, Hh / 32), 256>>>(W_s1, W_e1);

    dim3 gg(NTOT / BN, Mm / BM);                  // 24 x 8 = 192 CTAs
    gemm_kernel<<<gg, 256, GEMM_SMEM>>>(b_s1, w_s2, b_e1, out);

    dim3 ge(Nn / 64, Nn / 64, Bb);                // 8 x 8 x 2 = 128 CTAs
    end_kernel<<<ge, 256, END_SMEM>>>(w_e2, b_e2, out + Mm);
}